// round 12
// baseline (speedup 1.0000x reference)
#include <cuda_runtime.h>
#include <cuda_bf16.h>
#include <math.h>
#include <stdint.h>

// ---------------- problem constants ----------------
#define Bb   4
#define Qq   8192
#define Ee   256
#define Hh   8
#define HDd  32
#define VLENv 21760            // 128*128 + 64*64 + 32*32 + 16*16
#define MV   (Bb * VLENv)      // 87040  rows (value)
#define MQ   (Bb * Qq)         // 32768  rows (queries / samp)
#define KE   768               // extended K = 3 * 256 (split-bf16)

// ---------------- scratch (device globals; no allocation allowed) ----------------
__device__ float g_v   [(size_t)MV * Ee];     // value @ V_W^T      (~89 MB)
__device__ float g_off [(size_t)MQ * Ee];     // tanh offsets       (~34 MB)
__device__ float g_attn[(size_t)MQ * 128];    // attention logits   (~17 MB)

__device__ __nv_bfloat16 g_val_ext [(size_t)MV * KE];   // ~134 MB
__device__ __nv_bfloat16 g_q_ext   [(size_t)MQ * KE];   // ~50 MB
__device__ __nv_bfloat16 g_samp_ext[(size_t)MQ * KE];   // ~50 MB (written by sampler)
__device__ __nv_bfloat16 g_w_ext   [4][(size_t)256 * KE]; // V_W, off_W, attn_W, out_W

// ============================================================================
// Split-bf16 conversion: float[rows,256] -> bf16[rows,768]
// MODE 0 (activations): [hi | lo | hi]   MODE 1 (weights): [hi | hi | lo]
// Pairing over extended K: ah*wh + al*wh + ah*wl  (drops al*wl ~ 2^-16)
// ============================================================================
__device__ __forceinline__ void split_store(const float2& x,
                                            __nv_bfloat16* o, int mode)
{
    __nv_bfloat16 hx = __float2bfloat16(x.x);
    __nv_bfloat16 hy = __float2bfloat16(x.y);
    float lx = x.x - __bfloat162float(hx);
    float ly = x.y - __bfloat162float(hy);
    __nv_bfloat162 hi; hi.x = hx; hi.y = hy;
    __nv_bfloat162 lo; lo.x = __float2bfloat16(lx); lo.y = __float2bfloat16(ly);
    __nv_bfloat162* p = (__nv_bfloat162*)o;
    p[0]   = hi;
    p[128] = mode ? hi : lo;
    p[256] = mode ? lo : hi;
}

template<int MODE>
__global__ void convert_ext(const float* __restrict__ in,
                            __nv_bfloat16* __restrict__ out, int rows)
{
    int idx = blockIdx.x * blockDim.x + threadIdx.x;  // one float2 per thread
    if (idx >= rows * 128) return;
    int row = idx >> 7, j = idx & 127;
    float2 x = ((const float2*)in)[idx];
    split_store(x, out + (size_t)row * KE + j * 2, MODE);
}

// All 4 weight matrices in ONE launch (they are tiny; 4 separate launches
// were pure launch-overhead). Segments (float2 counts): 32768/32768/16384/32768.
__global__ void convert_w4(const float* __restrict__ w0, const float* __restrict__ w1,
                           const float* __restrict__ w2, const float* __restrict__ w3,
                           __nv_bfloat16* __restrict__ o0, __nv_bfloat16* __restrict__ o1,
                           __nv_bfloat16* __restrict__ o2, __nv_bfloat16* __restrict__ o3)
{
    int idx = blockIdx.x * 256 + threadIdx.x;
    const float* in; __nv_bfloat16* out; int local;
    if      (idx <  32768) { in = w0; out = o0; local = idx; }
    else if (idx <  65536) { in = w1; out = o1; local = idx -  32768; }
    else if (idx <  81920) { in = w2; out = o2; local = idx -  65536; }
    else if (idx < 114688) { in = w3; out = o3; local = idx -  81920; }
    else return;
    int row = local >> 7, j = local & 127;
    float2 x = ((const float2*)in)[local];
    split_store(x, out + (size_t)row * KE + j * 2, 1);
}

// ============================================================================
// HMMA GEMM (arch-neutral PTX: ldmatrix + mma.sync + cp.async, sm_80+ path)
//   C[M,N] = act( A_ext[M,768] @ W_ext[N,768]^T + bias )
// CTA tile 128x128xK64, 8 warps (4m x 2n), warp tile 32x64.
// SMEM: 2 stages x (A 16KB + B 16KB) = 64KB, SW128 xor swizzle.
// ============================================================================
#define STAGE_BYTES 32768
#define SMEM_TOTAL_MM (2 * STAGE_BYTES)

__device__ __forceinline__ uint32_t smem_u32(const void* p) {
    uint32_t a;
    asm("{ .reg .u64 t; cvta.to.shared.u64 t, %1; cvt.u32.u64 %0, t; }" : "=r"(a) : "l"(p));
    return a;
}
__device__ __forceinline__ void cp16(uint32_t s, const void* g) {
    asm volatile("cp.async.cg.shared.global [%0], [%1], 16;" :: "r"(s), "l"(g));
}
__device__ __forceinline__ void cp_commit() {
    asm volatile("cp.async.commit_group;" ::: "memory");
}
__device__ __forceinline__ void ldsm_x4(uint32_t* r, uint32_t addr) {
    asm volatile("ldmatrix.sync.aligned.m8n8.x4.shared.b16 {%0,%1,%2,%3}, [%4];"
                 : "=r"(r[0]), "=r"(r[1]), "=r"(r[2]), "=r"(r[3]) : "r"(addr));
}
__device__ __forceinline__ void mma16816(float* d, const uint32_t* a, const uint32_t* b) {
    asm volatile("mma.sync.aligned.m16n8k16.row.col.f32.bf16.bf16.f32 "
                 "{%0,%1,%2,%3}, {%4,%5,%6,%7}, {%8,%9}, {%0,%1,%2,%3};"
                 : "+f"(d[0]), "+f"(d[1]), "+f"(d[2]), "+f"(d[3])
                 : "r"(a[0]), "r"(a[1]), "r"(a[2]), "r"(a[3]), "r"(b[0]), "r"(b[1]));
}

template<int ACT, int WITH_BIAS>
__global__ void __launch_bounds__(256, 2) mm_hmma(
    const __nv_bfloat16* __restrict__ A,    // [M, 768] row-major
    const __nv_bfloat16* __restrict__ Wx,   // [N, 768] row-major
    const float* __restrict__ bias,
    float* __restrict__ C, int M, int N)
{
    extern __shared__ char smem[];
    const uint32_t sb = smem_u32(smem);

    const int tid  = threadIdx.x;
    const int wid  = tid >> 5;
    const int lane = tid & 31;
    const int wm   = wid & 3;            // 4 m-warps (32 rows each)
    const int wn   = wid >> 2;           // 2 n-warps (64 cols each)
    const int bm   = blockIdx.y * 128;
    const int bn   = blockIdx.x * 128;

    const char* Ab = (const char*)A  + (size_t)bm * (KE * 2);   // row = 1536 B
    const char* Wb = (const char*)Wx + (size_t)bn * (KE * 2);

    auto load_stage = [&](int c, int st) {
        const uint32_t sbuf = sb + st * STAGE_BYTES;
#pragma unroll
        for (int i = 0; i < 4; i++) {
            int u = i * 256 + tid;
            int row = u >> 3, ku = u & 7;
            uint32_t bo = row * 128 + ku * 16;
            uint32_t sw = bo ^ ((bo >> 3) & 0x70);
            cp16(sbuf + sw, Ab + (size_t)row * 1536 + c * 128 + ku * 16);
        }
#pragma unroll
        for (int i = 0; i < 4; i++) {
            int u = i * 256 + tid;
            int row = u >> 3, ku = u & 7;
            uint32_t bo = row * 128 + ku * 16;
            uint32_t sw = bo ^ ((bo >> 3) & 0x70);
            cp16(sbuf + 16384 + sw, Wb + (size_t)row * 1536 + c * 128 + ku * 16);
        }
        cp_commit();
    };

    float acc[2][8][4];
#pragma unroll
    for (int i = 0; i < 2; i++)
#pragma unroll
        for (int j = 0; j < 8; j++)
#pragma unroll
            for (int e = 0; e < 4; e++) acc[i][j][e] = 0.f;

    const uint32_t xorm = (uint32_t)(lane & 7) << 4;
    const int arow = wm * 32 + (lane & 15);
    const int ahi  = lane >> 4;
    const int brow = wn * 64 + ((lane >> 4) & 1) * 8 + (lane & 7);
    const int bhi  = (lane >> 3) & 1;

    load_stage(0, 0);
    load_stage(1, 1);

    for (int c = 0; c < 12; ++c) {
        if (c < 11) { asm volatile("cp.async.wait_group 1;" ::: "memory"); }
        else        { asm volatile("cp.async.wait_group 0;" ::: "memory"); }
        __syncthreads();

        const uint32_t sbuf  = sb + (c & 1) * STAGE_BYTES;
        const uint32_t sbufB = sbuf + 16384;

#pragma unroll
        for (int ks = 0; ks < 4; ks++) {
            uint32_t a[2][4];
#pragma unroll
            for (int mm = 0; mm < 2; mm++) {
                uint32_t bo = (uint32_t)(arow + mm * 16) * 128
                            + ((uint32_t)((ks * 2 + ahi) * 16) ^ xorm);
                ldsm_x4(a[mm], sbuf + bo);
            }
            uint32_t b[4][4];
#pragma unroll
            for (int jp = 0; jp < 4; jp++) {
                uint32_t bo = (uint32_t)(brow + jp * 16) * 128
                            + ((uint32_t)((ks * 2 + bhi) * 16) ^ xorm);
                ldsm_x4(b[jp], sbufB + bo);
            }
#pragma unroll
            for (int mm = 0; mm < 2; mm++)
#pragma unroll
                for (int jn = 0; jn < 8; jn++)
                    mma16816(acc[mm][jn], a[mm], &b[jn >> 1][(jn & 1) * 2]);
        }
        __syncthreads();
        if (c + 2 < 12) load_stage(c + 2, c & 1);
    }

    const int r0 = bm + wm * 32 + (lane >> 2);
    const int c0 = bn + wn * 64 + (lane & 3) * 2;
#pragma unroll
    for (int mm = 0; mm < 2; mm++) {
#pragma unroll
        for (int jn = 0; jn < 8; jn++) {
            const int row = r0 + mm * 16;
            const int col = c0 + jn * 8;
            float v0 = acc[mm][jn][0], v1 = acc[mm][jn][1];
            float v2 = acc[mm][jn][2], v3 = acc[mm][jn][3];
            if (WITH_BIAS) {
                float b0 = bias[col], b1 = bias[col + 1];
                v0 += b0; v1 += b1; v2 += b0; v3 += b1;
            }
            if (ACT == 1) {
                v0 = tanhf(v0); v1 = tanhf(v1); v2 = tanhf(v2); v3 = tanhf(v3);
            }
            *(float2*)(C + (size_t)row * N + col)       = make_float2(v0, v1);
            *(float2*)(C + (size_t)(row + 8) * N + col) = make_float2(v2, v3);
        }
    }
}

// ---------------------------------------------------------------------------
// Sampler v4: identical gather math to v3, but the epilogue writes the
// split-bf16 extended layout [hi | lo | hi] directly into g_samp_ext
// (same rounding the convert kernel performed -> identical numerics),
// killing a 34MB fp32 write + 34MB read + one kernel launch.
// ---------------------------------------------------------------------------
__global__ void __launch_bounds__(256) sampler_kernel(
    const float* __restrict__ v,
    const float* __restrict__ off,
    const float* __restrict__ attn,
    const float* __restrict__ refp,
    __nv_bfloat16* __restrict__ outp)   // [MQ, 768] ext layout
{
    __shared__ int   s_pos[8][16][4];
    __shared__ float s_w  [8][16][4];

    const int wslot = threadIdx.x >> 5;
    const int wid   = blockIdx.x * 8 + wslot;
    const int lane  = threadIdx.x & 31;
    const int h     = wid & 7;
    const size_t bq = (size_t)(wid >> 3);
    const int b     = wid >> 16;

    const int r   = lane & 15;
    const int lev = r >> 2;
    const int Wl  = 128 >> lev;
    const int start = (65536 - ((Wl * Wl) << 2)) / 3;

    float logit = attn[bq * 128 + h * 16 + r];
    float m = logit;
#pragma unroll
    for (int s = 1; s < 16; s <<= 1)
        m = fmaxf(m, __shfl_xor_sync(0xffffffffu, m, s));
    float e = __expf(logit - m);
    float ssum = e;
#pragma unroll
    for (int s = 1; s < 16; s <<= 1)
        ssum += __shfl_xor_sync(0xffffffffu, ssum, s);
    const float wgt = e / ssum;

    const float rx = refp[bq * 8 + lev * 2 + 0];
    const float ry = refp[bq * 8 + lev * 2 + 1];
    const float ox = off[bq * 256 + h * 32 + r * 2 + 0];
    const float oy = off[bq * 256 + h * 32 + r * 2 + 1];
    const float x = fminf(fmaxf(rx + ox, -1.f), 1.f);
    const float y = fminf(fmaxf(ry + oy, -1.f), 1.f);
    const float scale = 0.5f * (float)(Wl - 1);
    const float fx = (x + 1.f) * scale;
    const float fy = (y + 1.f) * scale;
    const float x0f = floorf(fx), y0f = floorf(fy);
    const float wx = fx - x0f,    wy = fy - y0f;
    const int x0 = min(max((int)x0f, 0), Wl - 1);
    const int x1 = min(x0 + 1, Wl - 1);
    const int y0 = min(max((int)y0f, 0), Wl - 1);
    const int y1 = min(y0 + 1, Wl - 1);

    if (lane < 16) {
        s_pos[wslot][r][0] = start + y0 * Wl + x0;
        s_pos[wslot][r][1] = start + y0 * Wl + x1;
        s_pos[wslot][r][2] = start + y1 * Wl + x0;
        s_pos[wslot][r][3] = start + y1 * Wl + x1;
        s_w  [wslot][r][0] = wgt * (1.f - wx) * (1.f - wy);
        s_w  [wslot][r][1] = wgt * wx * (1.f - wy);
        s_w  [wslot][r][2] = wgt * (1.f - wx) * wy;
        s_w  [wslot][r][3] = wgt * wx * wy;
    }
    __syncwarp();

    const int c = lane >> 3;
    const int k = lane & 7;
    const float* vbase = v + (size_t)b * VLENv * Ee + h * HDd + k * 4;

    float ax = 0.f, ay = 0.f, az = 0.f, aw = 0.f;
#pragma unroll
    for (int t = 0; t < 16; t++) {
        const int   pos = s_pos[wslot][t][c];
        const float wc  = s_w  [wslot][t][c];
        const float4 d = *(const float4*)(vbase + (size_t)pos * Ee);
        ax = fmaf(wc, d.x, ax);
        ay = fmaf(wc, d.y, ay);
        az = fmaf(wc, d.z, az);
        aw = fmaf(wc, d.w, aw);
    }
#pragma unroll
    for (int s = 8; s < 32; s <<= 1) {
        ax += __shfl_xor_sync(0xffffffffu, ax, s);
        ay += __shfl_xor_sync(0xffffffffu, ay, s);
        az += __shfl_xor_sync(0xffffffffu, az, s);
        aw += __shfl_xor_sync(0xffffffffu, aw, s);
    }

    if (lane < 8) {
        // split-bf16 ext store: hi @ col, lo @ col+256, hi @ col+512
        __nv_bfloat16 h0 = __float2bfloat16(ax);
        __nv_bfloat16 h1 = __float2bfloat16(ay);
        __nv_bfloat16 h2 = __float2bfloat16(az);
        __nv_bfloat16 h3 = __float2bfloat16(aw);
        union { __nv_bfloat162 v2[2]; uint2 u; } hi, lo;
        hi.v2[0].x = h0; hi.v2[0].y = h1; hi.v2[1].x = h2; hi.v2[1].y = h3;
        lo.v2[0].x = __float2bfloat16(ax - __bfloat162float(h0));
        lo.v2[0].y = __float2bfloat16(ay - __bfloat162float(h1));
        lo.v2[1].x = __float2bfloat16(az - __bfloat162float(h2));
        lo.v2[1].y = __float2bfloat16(aw - __bfloat162float(h3));
        __nv_bfloat16* o = outp + bq * KE + h * HDd + k * 4;
        *(uint2*)(o)       = hi.u;
        *(uint2*)(o + 256) = lo.u;
        *(uint2*)(o + 512) = hi.u;
    }
}

// ---------------------------------------------------------------------------
// kernel_launch — forked-graph schedule:
//   branch A (stream 0): conv_val -> GEMM1(value)
//   branch B (s1):       conv_w4, conv_q -> GEMM2(off) -> GEMM3(attn)
//   join -> sampler (writes samp_ext) -> GEMM4(out)
// inputs: 0 queries, 1 ref_points, 2 value, 3 spatial_shapes,
//         4 V_W, 5 off_W, 6 off_b, 7 attn_W, 8 attn_b, 9 out_W
// ---------------------------------------------------------------------------
extern "C" void kernel_launch(void* const* d_in, const int* in_sizes, int n_in,
                              void* d_out, int out_size)
{
    const float* queries = (const float*)d_in[0];
    const float* refp    = (const float*)d_in[1];
    const float* value   = (const float*)d_in[2];
    const float* V_W     = (const float*)d_in[4];
    const float* off_W   = (const float*)d_in[5];
    const float* off_b   = (const float*)d_in[6];
    const float* attn_W  = (const float*)d_in[7];
    const float* attn_b  = (const float*)d_in[8];
    const float* out_W   = (const float*)d_in[9];
    float* out = (float*)d_out;

    float *pv, *poff, *pattn;
    __nv_bfloat16 *pval_e, *pq_e, *psamp_e, *pw_e;
    cudaGetSymbolAddress((void**)&pv,      g_v);
    cudaGetSymbolAddress((void**)&poff,    g_off);
    cudaGetSymbolAddress((void**)&pattn,   g_attn);
    cudaGetSymbolAddress((void**)&pval_e,  g_val_ext);
    cudaGetSymbolAddress((void**)&pq_e,    g_q_ext);
    cudaGetSymbolAddress((void**)&psamp_e, g_samp_ext);
    cudaGetSymbolAddress((void**)&pw_e,    g_w_ext);
    __nv_bfloat16* w_v    = pw_e + 0 * (size_t)256 * KE;
    __nv_bfloat16* w_off  = pw_e + 1 * (size_t)256 * KE;
    __nv_bfloat16* w_attn = pw_e + 2 * (size_t)256 * KE;
    __nv_bfloat16* w_out  = pw_e + 3 * (size_t)256 * KE;

    cudaFuncSetAttribute(mm_hmma<0, 0>, cudaFuncAttributeMaxDynamicSharedMemorySize, SMEM_TOTAL_MM);
    cudaFuncSetAttribute(mm_hmma<1, 1>, cudaFuncAttributeMaxDynamicSharedMemorySize, SMEM_TOTAL_MM);
    cudaFuncSetAttribute(mm_hmma<0, 1>, cudaFuncAttributeMaxDynamicSharedMemorySize, SMEM_TOTAL_MM);

    // side stream + fork/join events (host objects; created per call — the
    // harness calls kernel_launch only a handful of times, replays the graph)
    cudaStream_t s1;
    cudaStreamCreateWithFlags(&s1, cudaStreamNonBlocking);
    cudaEvent_t eFork, eJoin;
    cudaEventCreateWithFlags(&eFork, cudaEventDisableTiming);
    cudaEventCreateWithFlags(&eJoin, cudaEventDisableTiming);

    cudaEventRecord(eFork, 0);
    cudaStreamWaitEvent(s1, eFork, 0);

    // ---- branch A (stream 0): value path
    convert_ext<0><<<(MV * 128 + 255) / 256, 256>>>(value, pval_e, MV);
    mm_hmma<0, 0><<<dim3(2, MV / 128), 256, SMEM_TOTAL_MM>>>(pval_e, w_v, nullptr, pv, MV, 256);

    // ---- branch B (s1): weights + query path
    convert_w4<<<448, 256, 0, s1>>>(V_W, off_W, attn_W, out_W, w_v, w_off, w_attn, w_out);
    convert_ext<0><<<(MQ * 128 + 255) / 256, 256, 0, s1>>>(queries, pq_e, MQ);
    mm_hmma<1, 1><<<dim3(2, MQ / 128), 256, SMEM_TOTAL_MM, s1>>>(pq_e, w_off, off_b, poff, MQ, 256);
    mm_hmma<0, 1><<<dim3(1, MQ / 128), 256, SMEM_TOTAL_MM, s1>>>(pq_e, w_attn, attn_b, pattn, MQ, 128);

    cudaEventRecord(eJoin, s1);
    cudaStreamWaitEvent(0, eJoin, 0);

    // ---- join: sampler (writes split-bf16 ext directly) -> final projection
    sampler_kernel<<<(Bb * Qq * Hh) / 8, 256>>>(pv, poff, pattn, refp, psamp_e);
    mm_hmma<0, 0><<<dim3(2, MQ / 128), 256, SMEM_TOTAL_MM>>>(psamp_e, w_out, nullptr, out, MQ, 256);
}